// round 3
// baseline (speedup 1.0000x reference)
#include <cuda_runtime.h>

// Issue-slot-bound kernel: pack per-component math into sm_10x f32x2 ops
// (FFMA2/FADD2 via inline PTX), single-wave 152x256 grid, 2 samples/thread.

typedef unsigned long long ull;

__device__ __forceinline__ ull pack2(float lo, float hi) {
    ull r; asm("mov.b64 %0, {%1, %2};" : "=l"(r) : "f"(lo), "f"(hi)); return r;
}
__device__ __forceinline__ void unpack2(ull p, float &lo, float &hi) {
    asm("mov.b64 {%0, %1}, %2;" : "=f"(lo), "=f"(hi) : "l"(p));
}
__device__ __forceinline__ ull fma2(ull a, ull b, ull c) {
    ull d; asm("fma.rn.f32x2 %0, %1, %2, %3;" : "=l"(d) : "l"(a), "l"(b), "l"(c)); return d;
}
__device__ __forceinline__ ull add2(ull a, ull b) {
    ull d; asm("add.rn.f32x2 %0, %1, %2;" : "=l"(d) : "l"(a), "l"(b)); return d;
}
__device__ __forceinline__ ull mul2(ull a, ull b) {
    ull d; asm("mul.rn.f32x2 %0, %1, %2;" : "=l"(d) : "l"(a), "l"(b)); return d;
}
// if (a > b) y += q;   (a = d0*v0, b = -d1*v1  =>  condition is d.v > 0)
__device__ __forceinline__ void cond_add2(ull &y, float a, float b, ull q) {
    asm("{\n\t"
        ".reg .pred p;\n\t"
        "setp.gt.f32 p, %1, %2;\n\t"
        "@p add.rn.f32x2 %0, %0, %3;\n\t"
        "}"
        : "+l"(y) : "f"(a), "f"(b), "l"(q));
}

__global__ __launch_bounds__(256) void strat_kernel(
    const float* __restrict__ X,
    const float* __restrict__ w,
    const float* __restrict__ b,
    const float* __restrict__ v,
    float* __restrict__ out,
    int n)   // n = number of samples
{
    const float w0 = w[0], w1 = w[1];
    const float bb = b[0];
    const float v0 = v[0], v1 = v[1];

    const float bm = bb - 1.0f;               // g-side: score - 1
    const float bp = bb + 1.0f;               // f-side: score + 1
    const ull hw01  = pack2( 0.5f * w0,  0.5f * w1);   //  +0.5*w
    const ull nhw01 = pack2(-0.5f * w0, -0.5f * w1);   //  -0.5*w
    const ull mqv01 = pack2(-0.475f * v0, -0.475f * v1); // -COST*(1-EPS)*v
    const ull c095  = pack2(0.95f, 0.95f);
    const ull vpm01 = pack2(v0, -v1);          // (v0, -v1) for sign test

    const int gt = blockIdx.x * blockDim.x + threadIdx.x;
    const int stride = gridDim.x * blockDim.x * 2;   // samples per pass

    #pragma unroll 1
    for (int base = 2 * gt; base < n; base += stride) {
        // two samples: base, base+1 (base always even -> float4/float2 aligned)
        const float4 q = *reinterpret_cast<const float4*>(X + 2 * base);
        float sx0[2] = {q.x, q.z};
        float sx1[2] = {q.y, q.w};

        ull x01[2], mX01[2], p05X[2], Xc01[2], A01[2];
        #pragma unroll
        for (int j = 0; j < 2; ++j) {
            x01[j]  = pack2(sx0[j], sx1[j]);         // CCP iterate starts at X (unclipped)
            mX01[j] = pack2(-sx0[j], -sx1[j]);
            p05X[j] = pack2(0.05f * sx0[j], 0.05f * sx1[j]);
            Xc01[j] = pack2(fminf(fmaxf(sx0[j], -10.f), 10.f),
                            fminf(fmaxf(sx1[j], -10.f), 10.f));
        }

        // rounds 0..10: fd at xt, 100 steps.  round 11: fd at XT, 200 steps (DELTA).
        #pragma unroll 1
        for (int round = 0; round < 12; ++round) {
            #pragma unroll
            for (int j = 0; j < 2; ++j) {
                float a0, a1; unpack2(x01[j], a0, a1);
                float st = __fmaf_rn(a0, w0, __fmaf_rn(a1, w1, bp));
                float ct = st * rsqrtf(__fmaf_rn(st, st, 1.0f));  // st/sqrt(st^2+1)
                // A = fd + 0.05*X = ct*0.5*w + 0.05*X
                A01[j] = fma2(pack2(ct, ct), hw01, p05X[j]);
                x01[j] = Xc01[j];                     // inner solve starts at clip(X)
            }
            const int nst = (round == 11) ? 200 : 100;
            #pragma unroll 2
            for (int k = 0; k < nst; ++k) {
                #pragma unroll
                for (int j = 0; j < 2; ++j) {
                    float a0, a1; unpack2(x01[j], a0, a1);
                    float s  = __fmaf_rn(a0, w0, __fmaf_rn(a1, w1, bm)); // score - 1
                    ull d01 = add2(x01[j], mX01[j]);                     // d = x - X
                    ull t2  = mul2(d01, vpm01);                          // (d0 v0, -d1 v1)
                    float sr = s * rsqrtf(__fmaf_rn(s, s, 1.0f));        // s/sqrt(s^2+1)
                    ull y = fma2(c095, x01[j], A01[j]);                  // 0.95x + A
                    y = fma2(pack2(sr, sr), nhw01, y);                   // - sr*0.5*w
                    float tl, th; unpack2(t2, tl, th);
                    cond_add2(y, tl, th, mqv01);                         // -[d.v>0]*0.475v
                    float y0, y1; unpack2(y, y0, y1);
                    x01[j] = pack2(fminf(fmaxf(y0, -10.f), 10.f),
                                   fminf(fmaxf(y1, -10.f), 10.f));
                }
            }
        }

        float r0a, r0b, r1a, r1b;
        unpack2(x01[0], r0a, r0b);
        unpack2(x01[1], r1a, r1b);
        float2 o;
        o.x = __fmaf_rn(r0a, w0, __fmaf_rn(r0b, w1, bb));
        o.y = __fmaf_rn(r1a, w0, __fmaf_rn(r1b, w1, bb));
        *reinterpret_cast<float2*>(out + base) = o;
    }
}

extern "C" void kernel_launch(void* const* d_in, const int* in_sizes, int n_in,
                              void* d_out, int out_size)
{
    const float* X = (const float*)d_in[0];  // [B, 2]
    const float* w = (const float*)d_in[1];  // [2]
    const float* b = (const float*)d_in[2];  // [1]
    const float* v = (const float*)d_in[3];  // [2]
    float* out = (float*)d_out;              // [B]

    int nsamples = in_sizes[0] / 2;
    // Single wave: 1 CTA per SM on GB300 (152 SMs), 2 samples/thread, 7 passes.
    strat_kernel<<<152, 256>>>(X, w, b, v, out, nsamples);
}